// round 16
// baseline (speedup 1.0000x reference)
#include <cuda_runtime.h>
#include <cuda_bf16.h>
#include <mma.h>
#include <math.h>

using namespace nvcuda;

// Problem constants
#define NTOK   2304     // 48*48 tokens
#define CDIM   256      // d_model
#define EDIM   512      // 2*d_model
#define HEADS  8
#define VHEADS 16       // heads * 2 softmax halves
#define DH     32       // per-half head dim
#define DV     64       // value dim per head

#define PADB 40         // Q/K bf16 smem row pitch (elements)
#define PADS 72         // S/V fp32 smem row pitch (floats)
// attn dynamic smem bytes:
//   Qhi/Qlo/Khi/Klo 4*(64*40*2) + Vs/Ss 2*(64*72*4) + Ls 128*4
#define ATTN_SMEM_BYTES (4*64*PADB*2 + 2*64*PADS*4 + 128*4)  // 56.5 KB -> 3 CTAs/SM

// ---------------------------------------------------------------------------
// Scratch (device globals)
// ---------------------------------------------------------------------------
__device__ float g_q[HEADS * NTOK * 64];
__device__ float g_k[HEADS * NTOK * 64];
__device__ float g_v[HEADS * NTOK * 64];
__device__ float g_o[VHEADS * NTOK * 64];
__device__ float g_oc[NTOK * EDIM];
__device__ float g_lam[HEADS];

// tf32 fragments (PV path)
typedef wmma::fragment<wmma::matrix_a, 16, 16, 8, wmma::precision::tf32, wmma::row_major> FragA;
typedef wmma::fragment<wmma::matrix_b, 16, 16, 8, wmma::precision::tf32, wmma::row_major> FragBr;
typedef wmma::fragment<wmma::accumulator, 16, 16, 8, float> FragC;

// bf16 fragments
typedef wmma::fragment<wmma::matrix_a, 16, 16, 16, __nv_bfloat16, wmma::row_major> HFragA;
typedef wmma::fragment<wmma::matrix_a, 16, 16, 16, __nv_bfloat16, wmma::col_major> HFragAc;
typedef wmma::fragment<wmma::matrix_b, 16, 16, 16, __nv_bfloat16, wmma::col_major> HFragBc;
typedef wmma::fragment<wmma::accumulator, 16, 16, 16, float> HFragC;

__device__ __forceinline__ void bf16_split(float f, __nv_bfloat16& hi, __nv_bfloat16& lo)
{
    hi = __float2bfloat16_rn(f);
    lo = __float2bfloat16_rn(f - __bfloat162float(hi));
}

// ---------------------------------------------------------------------------
// QKV projection, bf16 hi/lo-split 3-term wmma (R10 winner — unchanged).
// Y[n][e] = sum_c X[c*NTOK+n] * W[e*256+c]
// grid (36, 8, 3), 128 threads.
// ---------------------------------------------------------------------------
__global__ __launch_bounds__(128) void proj_tc_kernel(
    const float* __restrict__ X,
    const float* __restrict__ Wq,
    const float* __restrict__ Wk,
    const float* __restrict__ Wv)
{
    const int sel = blockIdx.z;
    const float* __restrict__ W = (sel == 0) ? Wq : (sel == 1) ? Wk : Wv;
    float* __restrict__ Y = (sel == 0) ? g_q : (sel == 1) ? g_k : g_v;

    __shared__ __nv_bfloat16 Xh[32 * 72], Xl[32 * 72];   // [c][n], n contiguous
    __shared__ __nv_bfloat16 Wh[64 * PADB], Wl[64 * PADB]; // [e][c], c contiguous

    const int tid = threadIdx.x;
    const int wid = tid >> 5;
    const int n0 = blockIdx.x * 64;
    const int hI = blockIdx.y;

    HFragC o[4];
    #pragma unroll
    for (int nt = 0; nt < 4; nt++) wmma::fill_fragment(o[nt], 0.0f);

    for (int c0 = 0; c0 < CDIM; c0 += 32) {
        __syncthreads();
        #pragma unroll
        for (int i = 0; i < 16; i++) {
            const int idx = tid + i * 128;
            const int c = idx >> 6, nl = idx & 63;
            bf16_split(X[(size_t)(c0 + c) * NTOK + n0 + nl],
                       Xh[c * 72 + nl], Xl[c * 72 + nl]);
        }
        #pragma unroll
        for (int i = 0; i < 16; i++) {
            const int idx = tid + i * 128;
            const int e = idx >> 5, cl = idx & 31;
            bf16_split(W[(size_t)(hI * 64 + e) * CDIM + c0 + cl],
                       Wh[e * PADB + cl], Wl[e * PADB + cl]);
        }
        __syncthreads();

        #pragma unroll
        for (int kt = 0; kt < 2; kt++) {
            HFragAc ah, al;
            wmma::load_matrix_sync(ah, Xh + (kt * 16) * 72 + wid * 16, 72);
            wmma::load_matrix_sync(al, Xl + (kt * 16) * 72 + wid * 16, 72);
            #pragma unroll
            for (int nt = 0; nt < 4; nt++) {
                HFragBc bh, bl;
                wmma::load_matrix_sync(bh, Wh + (nt * 16) * PADB + kt * 16, PADB);
                wmma::load_matrix_sync(bl, Wl + (nt * 16) * PADB + kt * 16, PADB);
                wmma::mma_sync(o[nt], ah, bh, o[nt]);
                wmma::mma_sync(o[nt], ah, bl, o[nt]);
                wmma::mma_sync(o[nt], al, bh, o[nt]);
            }
        }
    }

    float* Yb = Y + (size_t)hI * NTOK * 64;
    #pragma unroll
    for (int nt = 0; nt < 4; nt++)
        wmma::store_matrix_sync(Yb + (size_t)(n0 + wid * 16) * 64 + nt * 16,
                                o[nt], 64, wmma::mem_row_major);
}

// ---------------------------------------------------------------------------
// lambda[h]
// ---------------------------------------------------------------------------
__global__ void lam_kernel(const float* __restrict__ lq1, const float* __restrict__ lk1,
                           const float* __restrict__ lq2, const float* __restrict__ lk2)
{
    const int h = threadIdx.x >> 5, lane = threadIdx.x & 31;
    float p1 = lq1[h * DH + lane] * lk1[h * DH + lane];
    float p2 = lq2[h * DH + lane] * lk2[h * DH + lane];
    #pragma unroll
    for (int off = 16; off; off >>= 1) {
        p1 += __shfl_xor_sync(0xffffffffu, p1, off);
        p2 += __shfl_xor_sync(0xffffffffu, p2, off);
    }
    if (lane == 0) g_lam[h] = expf(p1) - expf(p2) + 0.8f;
}

// ---------------------------------------------------------------------------
// Tensor-core flash attention — R10 body byte-for-byte; ONLY change: no pair
// folding. One query block per CTA, grid (36, 16) = 576 CTAs so all 444
// smem-allowed resident slots (3 CTAs/SM x 148) fill — R10's grid of 288 left
// a third of the slots empty (~1.95 CTAs/SM measured arithmetic).
// Heavy-first: qb = 35 - bx so 36-tile blocks start at t=0.
// QK^T: bf16 hi/lo split. PV: tf32 pre-rounded. 56.5KB smem.
// ---------------------------------------------------------------------------
__global__ __launch_bounds__(128) void attn_tc_kernel()
{
    extern __shared__ float sm[];
    __nv_bfloat16* Qhi = (__nv_bfloat16*)sm;         // [64][PADB]
    __nv_bfloat16* Qlo = Qhi + 64 * PADB;            // [64][PADB]
    __nv_bfloat16* Khi = Qlo + 64 * PADB;            // [64][PADB]
    __nv_bfloat16* Klo = Khi + 64 * PADB;            // [64][PADB]
    float* Vs = (float*)(Klo + 64 * PADB);           // [64][PADS] tf32-rounded
    float* Ss = Vs + 64 * PADS;                      // [64][PADS] S / P / O
    float* Ls = Ss + 64 * PADS;                      // [2][64]

    const int vh   = blockIdx.y;
    const int h    = vh >> 1;
    const int half = vh & 1;

    const float* __restrict__ Qp = g_q + (size_t)h * NTOK * 64 + half * DH;
    const float* __restrict__ Kp = g_k + (size_t)h * NTOK * 64 + half * DH;
    const float* __restrict__ Vp = g_v + (size_t)h * NTOK * 64;
    float* __restrict__ Op       = g_o + (size_t)vh * NTOK * 64;

    const int tid = threadIdx.x;
    const int wid = tid >> 5;              // 0..3, 16-row q strip

    const float scale = 0.17677669529663687f;  // 1/sqrt(32)

    const int qb = 35 - (int)blockIdx.x;   // heavy blocks first
    const int n0 = qb * 64;

    // Stage Q (scaled) split into bf16 hi/lo: 64 x 32
    #pragma unroll
    for (int i = 0; i < 16; i++) {
        const int idx = tid + i * 128;
        const int r = idx >> 5, d = idx & 31;
        const float f = Qp[(size_t)(n0 + r) * 64 + d] * scale;
        bf16_split(f, Qhi[r * PADB + d], Qlo[r * PADB + d]);
    }
    __syncthreads();

    // Per-warp Q fragments (row-major, k16), loaded once
    HFragA qh[2], ql[2];
    #pragma unroll
    for (int kt = 0; kt < 2; kt++) {
        wmma::load_matrix_sync(qh[kt], Qhi + (wid * 16) * PADB + kt * 16, PADB);
        wmma::load_matrix_sync(ql[kt], Qlo + (wid * 16) * PADB + kt * 16, PADB);
    }

    FragC o_acc[4];
    #pragma unroll
    for (int nt = 0; nt < 4; nt++) wmma::fill_fragment(o_acc[nt], 0.0f);
    float lrow = 0.0f;

    const int kb_max = qb;
    for (int kb = 0; kb <= kb_max; kb++) {
        const int k0 = kb << 6;
        __syncthreads();   // previous tile's MMAs done reading Khi/Klo/Vs

        // Stage K 64x32, split bf16 hi/lo
        #pragma unroll
        for (int i = 0; i < 16; i++) {
            const int idx = tid + i * 128;
            const int r = idx >> 5, d = idx & 31;
            bf16_split(Kp[(size_t)(k0 + r) * 64 + d],
                       Khi[r * PADB + d], Klo[r * PADB + d]);
        }
        // Stage V 64x64, pre-rounded to tf32
        #pragma unroll
        for (int i = 0; i < 8; i++) {
            const int idx = tid + i * 128;
            const int r = idx >> 4, c4 = (idx & 15) * 4;
            float4 f = *(const float4*)&Vp[(size_t)(k0 + r) * 64 + c4];
            f.x = wmma::__float_to_tf32(f.x);
            f.y = wmma::__float_to_tf32(f.y);
            f.z = wmma::__float_to_tf32(f.z);
            f.w = wmma::__float_to_tf32(f.w);
            *(float4*)&Vs[r * PADS + c4] = f;
        }
        __syncthreads();

        // S = Q K^T via bf16 split: qh*kh + qh*kl + ql*kh
        HFragC s_acc[4];
        #pragma unroll
        for (int nt = 0; nt < 4; nt++) wmma::fill_fragment(s_acc[nt], 0.0f);
        #pragma unroll
        for (int kt = 0; kt < 2; kt++) {
            #pragma unroll
            for (int nt = 0; nt < 4; nt++) {
                HFragBc kh, kl;
                wmma::load_matrix_sync(kh, Khi + (nt * 16) * PADB + kt * 16, PADB);
                wmma::load_matrix_sync(kl, Klo + (nt * 16) * PADB + kt * 16, PADB);
                wmma::mma_sync(s_acc[nt], qh[kt], kh, s_acc[nt]);
                wmma::mma_sync(s_acc[nt], qh[kt], kl, s_acc[nt]);
                wmma::mma_sync(s_acc[nt], ql[kt], kh, s_acc[nt]);
            }
        }
        #pragma unroll
        for (int nt = 0; nt < 4; nt++)
            wmma::store_matrix_sync(Ss + (wid * 16) * PADS + nt * 16, s_acc[nt],
                                    PADS, wmma::mem_row_major);
        __syncthreads();

        // exp (+causal mask on diagonal), write tf32-rounded P, row sums
        {
            const int r  = tid & 63;
            const int co = (tid >> 6) * 32;
            float* row = Ss + r * PADS + co;
            if (kb == kb_max) {
                const int lim = n0 + r - k0 - co;   // valid while col <= lim
                #pragma unroll
                for (int i = 0; i < 8; i++) {
                    float4 f = *(float4*)&row[i * 4];
                    const int c = i * 4;
                    f.x = (c + 0 <= lim) ? wmma::__float_to_tf32(__expf(f.x)) : 0.0f;
                    f.y = (c + 1 <= lim) ? wmma::__float_to_tf32(__expf(f.y)) : 0.0f;
                    f.z = (c + 2 <= lim) ? wmma::__float_to_tf32(__expf(f.z)) : 0.0f;
                    f.w = (c + 3 <= lim) ? wmma::__float_to_tf32(__expf(f.w)) : 0.0f;
                    lrow += (f.x + f.y) + (f.z + f.w);
                    *(float4*)&row[i * 4] = f;
                }
            } else {
                #pragma unroll
                for (int i = 0; i < 8; i++) {
                    float4 f = *(float4*)&row[i * 4];
                    f.x = wmma::__float_to_tf32(__expf(f.x));
                    f.y = wmma::__float_to_tf32(__expf(f.y));
                    f.z = wmma::__float_to_tf32(__expf(f.z));
                    f.w = wmma::__float_to_tf32(__expf(f.w));
                    lrow += (f.x + f.y) + (f.z + f.w);
                    *(float4*)&row[i * 4] = f;
                }
            }
        }
        __syncthreads();

        // O += P @ V (tf32, pure mma; operands pre-rounded in smem)
        #pragma unroll
        for (int kt = 0; kt < 8; kt++) {
            FragA a;
            wmma::load_matrix_sync(a, Ss + (wid * 16) * PADS + kt * 8, PADS);
            #pragma unroll
            for (int nt = 0; nt < 4; nt++) {
                FragBr vb;
                wmma::load_matrix_sync(vb, Vs + (kt * 8) * PADS + nt * 16, PADS);
                wmma::mma_sync(o_acc[nt], a, vb, o_acc[nt]);
            }
        }
    }

    // Epilogue: O frags -> smem, combine l halves, normalize, store
    #pragma unroll
    for (int nt = 0; nt < 4; nt++)
        wmma::store_matrix_sync(Ss + (wid * 16) * PADS + nt * 16, o_acc[nt],
                                PADS, wmma::mem_row_major);
    Ls[(tid >> 6) * 64 + (tid & 63)] = lrow;
    __syncthreads();
    {
        const int r  = tid & 63;
        const int co = (tid >> 6) * 32;
        const float inv = 1.0f / (Ls[r] + Ls[64 + r]);
        const float* row = Ss + r * PADS + co;
        float* dst = Op + (size_t)(n0 + r) * 64 + co;
        #pragma unroll
        for (int i = 0; i < 8; i++) {
            float4 f = *(const float4*)&row[i * 4];
            f.x *= inv; f.y *= inv; f.z *= inv; f.w *= inv;
            *(float4*)&dst[i * 4] = f;
        }
    }
}

// ---------------------------------------------------------------------------
// Combine halves + RMS norm
// ---------------------------------------------------------------------------
__global__ __launch_bounds__(256) void combine_kernel(const float* __restrict__ rms_scale)
{
    const int n = blockIdx.x;
    const int h = threadIdx.x >> 5, lane = threadIdx.x & 31;
    const float lam = g_lam[h];

    const float* o1 = g_o + ((size_t)(2 * h) * NTOK + n) * 64;
    const float* o2 = g_o + ((size_t)(2 * h + 1) * NTOK + n) * 64;

    const float a = o1[lane]      - lam * o2[lane];
    const float b = o1[lane + 32] - lam * o2[lane + 32];

    float ss = a * a + b * b;
    #pragma unroll
    for (int off = 16; off; off >>= 1)
        ss += __shfl_xor_sync(0xffffffffu, ss, off);

    const float inv = rsqrtf(ss * (1.0f / 64.0f) + 1e-5f) * 0.2f;

    float* out = g_oc + (size_t)n * EDIM + h * 64;
    out[lane]      = a * inv * rms_scale[lane];
    out[lane + 32] = b * inv * rms_scale[lane + 32];
}

// ---------------------------------------------------------------------------
// Output projection, bf16 hi/lo-split 3-term wmma (R10 winner — unchanged).
// grid (36, 4), 128 threads.
// ---------------------------------------------------------------------------
__global__ __launch_bounds__(128) void out_tc_kernel(
    const float* __restrict__ Wo, float* __restrict__ out)
{
    __shared__ __nv_bfloat16 Ah[64 * PADB], Al[64 * PADB];  // Wo [c][e], e contiguous
    __shared__ __nv_bfloat16 Bh[64 * PADB], Bl[64 * PADB];  // oc [n][e], e contiguous

    const int tid = threadIdx.x;
    const int wid = tid >> 5;
    const int n0 = blockIdx.x * 64, c0 = blockIdx.y * 64;

    HFragC o[4];
    #pragma unroll
    for (int nt = 0; nt < 4; nt++) wmma::fill_fragment(o[nt], 0.0f);

    for (int e0 = 0; e0 < EDIM; e0 += 32) {
        __syncthreads();
        #pragma unroll
        for (int i = 0; i < 16; i++) {
            const int idx = tid + i * 128;
            const int cc = idx >> 5, el = idx & 31;
            bf16_split(Wo[(size_t)(c0 + cc) * EDIM + e0 + el],
                       Ah[cc * PADB + el], Al[cc * PADB + el]);
        }
        #pragma unroll
        for (int i = 0; i < 16; i++) {
            const int idx = tid + i * 128;
            const int nn = idx >> 5, el = idx & 31;
            bf16_split(g_oc[(size_t)(n0 + nn) * EDIM + e0 + el],
                       Bh[nn * PADB + el], Bl[nn * PADB + el]);
        }
        __syncthreads();

        #pragma unroll
        for (int kt = 0; kt < 2; kt++) {
            HFragA ah, al;   // (c, e) row-major
            wmma::load_matrix_sync(ah, Ah + (wid * 16) * PADB + kt * 16, PADB);
            wmma::load_matrix_sync(al, Al + (wid * 16) * PADB + kt * 16, PADB);
            #pragma unroll
            for (int nt = 0; nt < 4; nt++) {
                HFragBc bh, bl;  // (e, n) col-major view of oc[n][e]
                wmma::load_matrix_sync(bh, Bh + (nt * 16) * PADB + kt * 16, PADB);
                wmma::load_matrix_sync(bl, Bl + (nt * 16) * PADB + kt * 16, PADB);
                wmma::mma_sync(o[nt], ah, bh, o[nt]);
                wmma::mma_sync(o[nt], ah, bl, o[nt]);
                wmma::mma_sync(o[nt], al, bh, o[nt]);
            }
        }
    }

    #pragma unroll
    for (int nt = 0; nt < 4; nt++)
        wmma::store_matrix_sync(out + (size_t)(c0 + wid * 16) * NTOK + n0 + nt * 16,
                                o[nt], NTOK, wmma::mem_row_major);
}

// ---------------------------------------------------------------------------
// Launch
// ---------------------------------------------------------------------------
extern "C" void kernel_launch(void* const* d_in, const int* in_sizes, int n_in,
                              void* d_out, int out_size)
{
    const float* X   = (const float*)d_in[0];
    const float* Wq  = (const float*)d_in[1];
    const float* Wk  = (const float*)d_in[2];
    const float* Wv  = (const float*)d_in[3];
    const float* Wo  = (const float*)d_in[4];
    const float* lq1 = (const float*)d_in[5];
    const float* lk1 = (const float*)d_in[6];
    const float* lq2 = (const float*)d_in[7];
    const float* lk2 = (const float*)d_in[8];
    const float* rs  = (const float*)d_in[9];
    float* out = (float*)d_out;

    static bool attr_set = false;
    if (!attr_set) {
        cudaFuncSetAttribute(attn_tc_kernel,
                             cudaFuncAttributeMaxDynamicSharedMemorySize,
                             ATTN_SMEM_BYTES);
        attr_set = true;
    }

    proj_tc_kernel<<<dim3(NTOK / 64, EDIM / 64, 3), 128>>>(X, Wq, Wk, Wv);
    lam_kernel<<<1, 256>>>(lq1, lk1, lq2, lk2);
    attn_tc_kernel<<<dim3(36, VHEADS), 128, ATTN_SMEM_BYTES>>>();
    combine_kernel<<<NTOK, 256>>>(rs);
    out_tc_kernel<<<dim3(NTOK / 64, CDIM / 64), 128>>>(Wo, out);
}

// round 17
// speedup vs baseline: 1.3513x; 1.3513x over previous
#include <cuda_runtime.h>
#include <cuda_bf16.h>
#include <mma.h>
#include <math.h>

using namespace nvcuda;

// Problem constants
#define NTOK   2304     // 48*48 tokens
#define CDIM   256      // d_model
#define EDIM   512      // 2*d_model
#define HEADS  8
#define VHEADS 16       // heads * 2 softmax halves
#define DH     32       // per-half head dim
#define DV     64       // value dim per head

#define PADB 40         // Q/K bf16 smem row pitch (elements)
#define PADS 72         // S/V fp32 smem row pitch (floats)
// attn dynamic smem bytes:
//   Qhi/Qlo/Khi/Klo 4*(64*40*2) + Vs/Ss 2*(64*72*4) + Ls 128*4
#define ATTN_SMEM_BYTES (4*64*PADB*2 + 2*64*PADS*4 + 128*4)  // 56.5 KB -> 3 CTAs/SM

// ---------------------------------------------------------------------------
// Scratch (device globals)
// ---------------------------------------------------------------------------
__device__ float g_q[HEADS * NTOK * 64];
__device__ float g_k[HEADS * NTOK * 64];
__device__ float g_v[HEADS * NTOK * 64];
__device__ float g_o[VHEADS * NTOK * 64];
__device__ float g_oc[NTOK * EDIM];
__device__ float g_lam[HEADS];

// tf32 fragments (PV path)
typedef wmma::fragment<wmma::matrix_a, 16, 16, 8, wmma::precision::tf32, wmma::row_major> FragA;
typedef wmma::fragment<wmma::matrix_b, 16, 16, 8, wmma::precision::tf32, wmma::row_major> FragBr;
typedef wmma::fragment<wmma::accumulator, 16, 16, 8, float> FragC;

// bf16 fragments
typedef wmma::fragment<wmma::matrix_a, 16, 16, 16, __nv_bfloat16, wmma::row_major> HFragA;
typedef wmma::fragment<wmma::matrix_a, 16, 16, 16, __nv_bfloat16, wmma::col_major> HFragAc;
typedef wmma::fragment<wmma::matrix_b, 16, 16, 16, __nv_bfloat16, wmma::col_major> HFragBc;
typedef wmma::fragment<wmma::accumulator, 16, 16, 16, float> HFragC;

__device__ __forceinline__ void bf16_split(float f, __nv_bfloat16& hi, __nv_bfloat16& lo)
{
    hi = __float2bfloat16_rn(f);
    lo = __float2bfloat16_rn(f - __bfloat162float(hi));
}

// ---------------------------------------------------------------------------
// QKV projection, bf16 hi/lo-split 3-term wmma (R10 winner — unchanged).
// Y[n][e] = sum_c X[c*NTOK+n] * W[e*256+c]
// grid (36, 8, 3), 128 threads.
// ---------------------------------------------------------------------------
__global__ __launch_bounds__(128) void proj_tc_kernel(
    const float* __restrict__ X,
    const float* __restrict__ Wq,
    const float* __restrict__ Wk,
    const float* __restrict__ Wv)
{
    const int sel = blockIdx.z;
    const float* __restrict__ W = (sel == 0) ? Wq : (sel == 1) ? Wk : Wv;
    float* __restrict__ Y = (sel == 0) ? g_q : (sel == 1) ? g_k : g_v;

    __shared__ __nv_bfloat16 Xh[32 * 72], Xl[32 * 72];   // [c][n], n contiguous
    __shared__ __nv_bfloat16 Wh[64 * PADB], Wl[64 * PADB]; // [e][c], c contiguous

    const int tid = threadIdx.x;
    const int wid = tid >> 5;
    const int n0 = blockIdx.x * 64;
    const int hI = blockIdx.y;

    HFragC o[4];
    #pragma unroll
    for (int nt = 0; nt < 4; nt++) wmma::fill_fragment(o[nt], 0.0f);

    for (int c0 = 0; c0 < CDIM; c0 += 32) {
        __syncthreads();
        #pragma unroll
        for (int i = 0; i < 16; i++) {
            const int idx = tid + i * 128;
            const int c = idx >> 6, nl = idx & 63;
            bf16_split(X[(size_t)(c0 + c) * NTOK + n0 + nl],
                       Xh[c * 72 + nl], Xl[c * 72 + nl]);
        }
        #pragma unroll
        for (int i = 0; i < 16; i++) {
            const int idx = tid + i * 128;
            const int e = idx >> 5, cl = idx & 31;
            bf16_split(W[(size_t)(hI * 64 + e) * CDIM + c0 + cl],
                       Wh[e * PADB + cl], Wl[e * PADB + cl]);
        }
        __syncthreads();

        #pragma unroll
        for (int kt = 0; kt < 2; kt++) {
            HFragAc ah, al;
            wmma::load_matrix_sync(ah, Xh + (kt * 16) * 72 + wid * 16, 72);
            wmma::load_matrix_sync(al, Xl + (kt * 16) * 72 + wid * 16, 72);
            #pragma unroll
            for (int nt = 0; nt < 4; nt++) {
                HFragBc bh, bl;
                wmma::load_matrix_sync(bh, Wh + (nt * 16) * PADB + kt * 16, PADB);
                wmma::load_matrix_sync(bl, Wl + (nt * 16) * PADB + kt * 16, PADB);
                wmma::mma_sync(o[nt], ah, bh, o[nt]);
                wmma::mma_sync(o[nt], ah, bl, o[nt]);
                wmma::mma_sync(o[nt], al, bh, o[nt]);
            }
        }
    }

    float* Yb = Y + (size_t)hI * NTOK * 64;
    #pragma unroll
    for (int nt = 0; nt < 4; nt++)
        wmma::store_matrix_sync(Yb + (size_t)(n0 + wid * 16) * 64 + nt * 16,
                                o[nt], 64, wmma::mem_row_major);
}

// ---------------------------------------------------------------------------
// lambda[h]
// ---------------------------------------------------------------------------
__global__ void lam_kernel(const float* __restrict__ lq1, const float* __restrict__ lk1,
                           const float* __restrict__ lq2, const float* __restrict__ lk2)
{
    const int h = threadIdx.x >> 5, lane = threadIdx.x & 31;
    float p1 = lq1[h * DH + lane] * lk1[h * DH + lane];
    float p2 = lq2[h * DH + lane] * lk2[h * DH + lane];
    #pragma unroll
    for (int off = 16; off; off >>= 1) {
        p1 += __shfl_xor_sync(0xffffffffu, p1, off);
        p2 += __shfl_xor_sync(0xffffffffu, p2, off);
    }
    if (lane == 0) g_lam[h] = expf(p1) - expf(p2) + 0.8f;
}

// ---------------------------------------------------------------------------
// Tensor-core flash attention — R10 body byte-for-byte (single pass).
// SCHEDULING FIX vs R15: 1D grid of 576, global heavy-first mapping
//   qb = 35 - bid/16, vh = bid%16
// so the first 444 dispatched CTAs (= all resident slots at 3 CTAs/SM) are
// exactly the 444 heaviest blocks across ALL vheads, and the tail is only
// qb 0..7 (<=8 tiles). R15's (36,16) grid dispatched x-fastest, starving
// vheads 13-15's heavy blocks until the end (+73us makespan).
// QK^T: bf16 hi/lo split. PV: tf32 pre-rounded. 56.5KB smem.
// ---------------------------------------------------------------------------
__global__ __launch_bounds__(128) void attn_tc_kernel()
{
    extern __shared__ float sm[];
    __nv_bfloat16* Qhi = (__nv_bfloat16*)sm;         // [64][PADB]
    __nv_bfloat16* Qlo = Qhi + 64 * PADB;            // [64][PADB]
    __nv_bfloat16* Khi = Qlo + 64 * PADB;            // [64][PADB]
    __nv_bfloat16* Klo = Khi + 64 * PADB;            // [64][PADB]
    float* Vs = (float*)(Klo + 64 * PADB);           // [64][PADS] tf32-rounded
    float* Ss = Vs + 64 * PADS;                      // [64][PADS] S / P / O
    float* Ls = Ss + 64 * PADS;                      // [2][64]

    const int bid  = (int)blockIdx.x;
    const int qb   = 35 - (bid >> 4);      // heavy blocks dispatched first
    const int vh   = bid & 15;
    const int h    = vh >> 1;
    const int half = vh & 1;

    const float* __restrict__ Qp = g_q + (size_t)h * NTOK * 64 + half * DH;
    const float* __restrict__ Kp = g_k + (size_t)h * NTOK * 64 + half * DH;
    const float* __restrict__ Vp = g_v + (size_t)h * NTOK * 64;
    float* __restrict__ Op       = g_o + (size_t)vh * NTOK * 64;

    const int tid = threadIdx.x;
    const int wid = tid >> 5;              // 0..3, 16-row q strip

    const float scale = 0.17677669529663687f;  // 1/sqrt(32)
    const int n0 = qb * 64;

    // Stage Q (scaled) split into bf16 hi/lo: 64 x 32
    #pragma unroll
    for (int i = 0; i < 16; i++) {
        const int idx = tid + i * 128;
        const int r = idx >> 5, d = idx & 31;
        const float f = Qp[(size_t)(n0 + r) * 64 + d] * scale;
        bf16_split(f, Qhi[r * PADB + d], Qlo[r * PADB + d]);
    }
    __syncthreads();

    // Per-warp Q fragments (row-major, k16), loaded once
    HFragA qh[2], ql[2];
    #pragma unroll
    for (int kt = 0; kt < 2; kt++) {
        wmma::load_matrix_sync(qh[kt], Qhi + (wid * 16) * PADB + kt * 16, PADB);
        wmma::load_matrix_sync(ql[kt], Qlo + (wid * 16) * PADB + kt * 16, PADB);
    }

    FragC o_acc[4];
    #pragma unroll
    for (int nt = 0; nt < 4; nt++) wmma::fill_fragment(o_acc[nt], 0.0f);
    float lrow = 0.0f;

    const int kb_max = qb;
    for (int kb = 0; kb <= kb_max; kb++) {
        const int k0 = kb << 6;
        __syncthreads();   // previous tile's MMAs done reading Khi/Klo/Vs

        // Stage K 64x32, split bf16 hi/lo
        #pragma unroll
        for (int i = 0; i < 16; i++) {
            const int idx = tid + i * 128;
            const int r = idx >> 5, d = idx & 31;
            bf16_split(Kp[(size_t)(k0 + r) * 64 + d],
                       Khi[r * PADB + d], Klo[r * PADB + d]);
        }
        // Stage V 64x64, pre-rounded to tf32
        #pragma unroll
        for (int i = 0; i < 8; i++) {
            const int idx = tid + i * 128;
            const int r = idx >> 4, c4 = (idx & 15) * 4;
            float4 f = *(const float4*)&Vp[(size_t)(k0 + r) * 64 + c4];
            f.x = wmma::__float_to_tf32(f.x);
            f.y = wmma::__float_to_tf32(f.y);
            f.z = wmma::__float_to_tf32(f.z);
            f.w = wmma::__float_to_tf32(f.w);
            *(float4*)&Vs[r * PADS + c4] = f;
        }
        __syncthreads();

        // S = Q K^T via bf16 split: qh*kh + qh*kl + ql*kh
        HFragC s_acc[4];
        #pragma unroll
        for (int nt = 0; nt < 4; nt++) wmma::fill_fragment(s_acc[nt], 0.0f);
        #pragma unroll
        for (int kt = 0; kt < 2; kt++) {
            #pragma unroll
            for (int nt = 0; nt < 4; nt++) {
                HFragBc kh, kl;
                wmma::load_matrix_sync(kh, Khi + (nt * 16) * PADB + kt * 16, PADB);
                wmma::load_matrix_sync(kl, Klo + (nt * 16) * PADB + kt * 16, PADB);
                wmma::mma_sync(s_acc[nt], qh[kt], kh, s_acc[nt]);
                wmma::mma_sync(s_acc[nt], qh[kt], kl, s_acc[nt]);
                wmma::mma_sync(s_acc[nt], ql[kt], kh, s_acc[nt]);
            }
        }
        #pragma unroll
        for (int nt = 0; nt < 4; nt++)
            wmma::store_matrix_sync(Ss + (wid * 16) * PADS + nt * 16, s_acc[nt],
                                    PADS, wmma::mem_row_major);
        __syncthreads();

        // exp (+causal mask on diagonal), write tf32-rounded P, row sums
        {
            const int r  = tid & 63;
            const int co = (tid >> 6) * 32;
            float* row = Ss + r * PADS + co;
            if (kb == kb_max) {
                const int lim = n0 + r - k0 - co;   // valid while col <= lim
                #pragma unroll
                for (int i = 0; i < 8; i++) {
                    float4 f = *(float4*)&row[i * 4];
                    const int c = i * 4;
                    f.x = (c + 0 <= lim) ? wmma::__float_to_tf32(__expf(f.x)) : 0.0f;
                    f.y = (c + 1 <= lim) ? wmma::__float_to_tf32(__expf(f.y)) : 0.0f;
                    f.z = (c + 2 <= lim) ? wmma::__float_to_tf32(__expf(f.z)) : 0.0f;
                    f.w = (c + 3 <= lim) ? wmma::__float_to_tf32(__expf(f.w)) : 0.0f;
                    lrow += (f.x + f.y) + (f.z + f.w);
                    *(float4*)&row[i * 4] = f;
                }
            } else {
                #pragma unroll
                for (int i = 0; i < 8; i++) {
                    float4 f = *(float4*)&row[i * 4];
                    f.x = wmma::__float_to_tf32(__expf(f.x));
                    f.y = wmma::__float_to_tf32(__expf(f.y));
                    f.z = wmma::__float_to_tf32(__expf(f.z));
                    f.w = wmma::__float_to_tf32(__expf(f.w));
                    lrow += (f.x + f.y) + (f.z + f.w);
                    *(float4*)&row[i * 4] = f;
                }
            }
        }
        __syncthreads();

        // O += P @ V (tf32, pure mma; operands pre-rounded in smem)
        #pragma unroll
        for (int kt = 0; kt < 8; kt++) {
            FragA a;
            wmma::load_matrix_sync(a, Ss + (wid * 16) * PADS + kt * 8, PADS);
            #pragma unroll
            for (int nt = 0; nt < 4; nt++) {
                FragBr vb;
                wmma::load_matrix_sync(vb, Vs + (kt * 8) * PADS + nt * 16, PADS);
                wmma::mma_sync(o_acc[nt], a, vb, o_acc[nt]);
            }
        }
    }

    // Epilogue: O frags -> smem, combine l halves, normalize, store
    #pragma unroll
    for (int nt = 0; nt < 4; nt++)
        wmma::store_matrix_sync(Ss + (wid * 16) * PADS + nt * 16, o_acc[nt],
                                PADS, wmma::mem_row_major);
    Ls[(tid >> 6) * 64 + (tid & 63)] = lrow;
    __syncthreads();
    {
        const int r  = tid & 63;
        const int co = (tid >> 6) * 32;
        const float inv = 1.0f / (Ls[r] + Ls[64 + r]);
        const float* row = Ss + r * PADS + co;
        float* dst = Op + (size_t)(n0 + r) * 64 + co;
        #pragma unroll
        for (int i = 0; i < 8; i++) {
            float4 f = *(const float4*)&row[i * 4];
            f.x *= inv; f.y *= inv; f.z *= inv; f.w *= inv;
            *(float4*)&dst[i * 4] = f;
        }
    }
}

// ---------------------------------------------------------------------------
// Combine halves + RMS norm
// ---------------------------------------------------------------------------
__global__ __launch_bounds__(256) void combine_kernel(const float* __restrict__ rms_scale)
{
    const int n = blockIdx.x;
    const int h = threadIdx.x >> 5, lane = threadIdx.x & 31;
    const float lam = g_lam[h];

    const float* o1 = g_o + ((size_t)(2 * h) * NTOK + n) * 64;
    const float* o2 = g_o + ((size_t)(2 * h + 1) * NTOK + n) * 64;

    const float a = o1[lane]      - lam * o2[lane];
    const float b = o1[lane + 32] - lam * o2[lane + 32];

    float ss = a * a + b * b;
    #pragma unroll
    for (int off = 16; off; off >>= 1)
        ss += __shfl_xor_sync(0xffffffffu, ss, off);

    const float inv = rsqrtf(ss * (1.0f / 64.0f) + 1e-5f) * 0.2f;

    float* out = g_oc + (size_t)n * EDIM + h * 64;
    out[lane]      = a * inv * rms_scale[lane];
    out[lane + 32] = b * inv * rms_scale[lane + 32];
}

// ---------------------------------------------------------------------------
// Output projection, bf16 hi/lo-split 3-term wmma (R10 winner — unchanged).
// grid (36, 4), 128 threads.
// ---------------------------------------------------------------------------
__global__ __launch_bounds__(128) void out_tc_kernel(
    const float* __restrict__ Wo, float* __restrict__ out)
{
    __shared__ __nv_bfloat16 Ah[64 * PADB], Al[64 * PADB];  // Wo [c][e], e contiguous
    __shared__ __nv_bfloat16 Bh[64 * PADB], Bl[64 * PADB];  // oc [n][e], e contiguous

    const int tid = threadIdx.x;
    const int wid = tid >> 5;
    const int n0 = blockIdx.x * 64, c0 = blockIdx.y * 64;

    HFragC o[4];
    #pragma unroll
    for (int nt = 0; nt < 4; nt++) wmma::fill_fragment(o[nt], 0.0f);

    for (int e0 = 0; e0 < EDIM; e0 += 32) {
        __syncthreads();
        #pragma unroll
        for (int i = 0; i < 16; i++) {
            const int idx = tid + i * 128;
            const int cc = idx >> 5, el = idx & 31;
            bf16_split(Wo[(size_t)(c0 + cc) * EDIM + e0 + el],
                       Ah[cc * PADB + el], Al[cc * PADB + el]);
        }
        #pragma unroll
        for (int i = 0; i < 16; i++) {
            const int idx = tid + i * 128;
            const int nn = idx >> 5, el = idx & 31;
            bf16_split(g_oc[(size_t)(n0 + nn) * EDIM + e0 + el],
                       Bh[nn * PADB + el], Bl[nn * PADB + el]);
        }
        __syncthreads();

        #pragma unroll
        for (int kt = 0; kt < 2; kt++) {
            HFragA ah, al;   // (c, e) row-major
            wmma::load_matrix_sync(ah, Ah + (wid * 16) * PADB + kt * 16, PADB);
            wmma::load_matrix_sync(al, Al + (wid * 16) * PADB + kt * 16, PADB);
            #pragma unroll
            for (int nt = 0; nt < 4; nt++) {
                HFragBc bh, bl;  // (e, n) col-major view of oc[n][e]
                wmma::load_matrix_sync(bh, Bh + (nt * 16) * PADB + kt * 16, PADB);
                wmma::load_matrix_sync(bl, Bl + (nt * 16) * PADB + kt * 16, PADB);
                wmma::mma_sync(o[nt], ah, bh, o[nt]);
                wmma::mma_sync(o[nt], ah, bl, o[nt]);
                wmma::mma_sync(o[nt], al, bh, o[nt]);
            }
        }
    }

    #pragma unroll
    for (int nt = 0; nt < 4; nt++)
        wmma::store_matrix_sync(out + (size_t)(c0 + wid * 16) * NTOK + n0 + nt * 16,
                                o[nt], NTOK, wmma::mem_row_major);
}

// ---------------------------------------------------------------------------
// Launch
// ---------------------------------------------------------------------------
extern "C" void kernel_launch(void* const* d_in, const int* in_sizes, int n_in,
                              void* d_out, int out_size)
{
    const float* X   = (const float*)d_in[0];
    const float* Wq  = (const float*)d_in[1];
    const float* Wk  = (const float*)d_in[2];
    const float* Wv  = (const float*)d_in[3];
    const float* Wo  = (const float*)d_in[4];
    const float* lq1 = (const float*)d_in[5];
    const float* lk1 = (const float*)d_in[6];
    const float* lq2 = (const float*)d_in[7];
    const float* lk2 = (const float*)d_in[8];
    const float* rs  = (const float*)d_in[9];
    float* out = (float*)d_out;

    static bool attr_set = false;
    if (!attr_set) {
        cudaFuncSetAttribute(attn_tc_kernel,
                             cudaFuncAttributeMaxDynamicSharedMemorySize,
                             ATTN_SMEM_BYTES);
        attr_set = true;
    }

    proj_tc_kernel<<<dim3(NTOK / 64, EDIM / 64, 3), 128>>>(X, Wq, Wk, Wv);
    lam_kernel<<<1, 256>>>(lq1, lk1, lq2, lk2);
    attn_tc_kernel<<<36 * VHEADS, 128, ATTN_SMEM_BYTES>>>();
    combine_kernel<<<NTOK, 256>>>(rs);
    out_tc_kernel<<<dim3(NTOK / 64, CDIM / 64), 128>>>(Wo, out);
}